// round 1
// baseline (speedup 1.0000x reference)
#include <cuda_runtime.h>
#include <math.h>

#define D 128
#define MAXN 50000

static const long SZ = (long)MAXN * D;   // 6,400,000 floats per feature buffer

// Scratch layout (single __device__ symbol, offsets in floats):
//  0..5  : Axn, Ahn, Axu, Ahu, Acn, Acu   (aggregation accumulators)
//  6..11 : Zn, Zu, CXn, CXu, HRn, HRu
//  then  : Wzr_n(512*256), Wzr_u(512*256), Wcx_n(256*128), Wcx_u, Wch_n, Wch_u
//  then  : bzr_n(256), bzr_u(256), bcx_n(128), bcx_u(128), bch_n(128), bch_u(128)
__device__ float g_buf[12L * 50000L * 128L + 2 * (512 * 256) + 4 * (256 * 128) + 2 * 256 + 4 * 128];
__device__ int g_deg[2 * MAXN];

// ---------------------------------------------------------------------------
// zero scratch accumulators + degree counters
__global__ void zero_kernel(float4* p, long n4, int* d, int nd) {
    long stride = (long)gridDim.x * blockDim.x;
    long i0 = blockIdx.x * (long)blockDim.x + threadIdx.x;
    for (long j = i0; j < n4; j += stride) p[j] = make_float4(0.f, 0.f, 0.f, 0.f);
    for (long j = i0; j < nd; j += stride) d[j] = 0;
}

// ---------------------------------------------------------------------------
__global__ void count_deg(const int* __restrict__ dst, int E, int* __restrict__ deg) {
    int i = blockIdx.x * blockDim.x + threadIdx.x;
    if (i < E) atomicAdd(&deg[dst[i]], 1);
}

// warp-per-edge: scatter-add two feature rows (x and h) of the source node
__global__ void agg2_kernel(const float* __restrict__ fx, const float* __restrict__ fh,
                            const int* __restrict__ src, const int* __restrict__ dst, int E,
                            float* __restrict__ Ax, float* __restrict__ Ah) {
    long gid = blockIdx.x * (long)blockDim.x + threadIdx.x;
    int e = (int)(gid >> 5);
    int lane = (int)(gid & 31);
    if (e >= E) return;
    int s = src[e], d = dst[e];
    float4 vx = *(const float4*)(fx + (long)s * D + lane * 4);
    float4 vh = *(const float4*)(fh + (long)s * D + lane * 4);
#if __CUDA_ARCH__ >= 900
    atomicAdd((float4*)(Ax + (long)d * D + lane * 4), vx);
    atomicAdd((float4*)(Ah + (long)d * D + lane * 4), vh);
#else
    float* ax = Ax + (long)d * D + lane * 4;
    float* ah = Ah + (long)d * D + lane * 4;
    atomicAdd(ax + 0, vx.x); atomicAdd(ax + 1, vx.y); atomicAdd(ax + 2, vx.z); atomicAdd(ax + 3, vx.w);
    atomicAdd(ah + 0, vh.x); atomicAdd(ah + 1, vh.y); atomicAdd(ah + 2, vh.z); atomicAdd(ah + 3, vh.w);
#endif
}

__global__ void agg1_kernel(const float* __restrict__ f,
                            const int* __restrict__ src, const int* __restrict__ dst, int E,
                            float* __restrict__ A) {
    long gid = blockIdx.x * (long)blockDim.x + threadIdx.x;
    int e = (int)(gid >> 5);
    int lane = (int)(gid & 31);
    if (e >= E) return;
    int s = src[e], d = dst[e];
    float4 v = *(const float4*)(f + (long)s * D + lane * 4);
#if __CUDA_ARCH__ >= 900
    atomicAdd((float4*)(A + (long)d * D + lane * 4), v);
#else
    float* a = A + (long)d * D + lane * 4;
    atomicAdd(a + 0, v.x); atomicAdd(a + 1, v.y); atomicAdd(a + 2, v.z); atomicAdd(a + 3, v.w);
#endif
}

// divide accumulated sums by max(deg,1) — two buffers at once
__global__ void norm2_kernel(float* __restrict__ A, float* __restrict__ B,
                             const int* __restrict__ deg, int n) {
    int i = blockIdx.x * blockDim.x + threadIdx.x;   // one float4 per thread
    int total = n * (D / 4);
    if (i >= total) return;
    int node = i >> 5;
    float inv = 1.f / (float)max(deg[node], 1);
    float4* a = (float4*)A + i;
    float4 va = *a; va.x *= inv; va.y *= inv; va.z *= inv; va.w *= inv; *a = va;
    float4* b = (float4*)B + i;
    float4 vb = *b; vb.x *= inv; vb.y *= inv; vb.z *= inv; vb.w *= inv; *b = vb;
}

__global__ void norm1_kernel(float* __restrict__ A, const int* __restrict__ deg, int n) {
    int i = blockIdx.x * blockDim.x + threadIdx.x;
    int total = n * (D / 4);
    if (i >= total) return;
    int node = i >> 5;
    float inv = 1.f / (float)max(deg[node], 1);
    float4* a = (float4*)A + i;
    float4 va = *a; va.x *= inv; va.y *= inv; va.z *= inv; va.w *= inv; *a = va;
}

// ---------------------------------------------------------------------------
// weight stacking
// Wzr [512,256]: rows: [Wl[gz..],[Wr[gz]],[Wl[gz+1]],[Wr[gz+1]]; cols<128 -> gz=0 (z), else gz=2 (r)
__global__ void build_wzr(const float* __restrict__ Wl, const float* __restrict__ Wr,
                          float* __restrict__ out, int t) {
    int j = blockIdx.x * blockDim.x + threadIdx.x;
    if (j >= 512 * 256) return;
    int k = j >> 8;
    int c = j & 255;
    int gz = (c < 128) ? 0 : 2;
    int cc = c & 127;
    int part = k >> 7;
    int kk = k & 127;
    int g = gz + (part >> 1);
    const float* src = (part & 1) ? Wr : Wl;
    out[j] = src[(((long)(g * 2 + t)) * 128 + kk) * 128 + cc];
}

// W2 [256,128]: rows [Wl[g]; Wr[g]]
__global__ void build_w2(const float* __restrict__ Wl, const float* __restrict__ Wr,
                         float* __restrict__ out, int g, int t) {
    int j = blockIdx.x * blockDim.x + threadIdx.x;
    if (j >= 256 * 128) return;
    int k = j >> 7;
    int c = j & 127;
    int part = k >> 7;
    int kk = k & 127;
    const float* src = part ? Wr : Wl;
    out[j] = src[(((long)(g * 2 + t)) * 128 + kk) * 128 + c];
}

__global__ void build_bias(const float* __restrict__ b,
                           float* bzr_n, float* bzr_u, float* bcx_n, float* bcx_u,
                           float* bch_n, float* bch_u) {
    int c = threadIdx.x;
    if (c >= 128) return;
#define BB(g, t) b[((g) * 2 + (t)) * 128 + c]
    bzr_n[c]       = BB(0, 0) + BB(1, 0);
    bzr_n[128 + c] = BB(2, 0) + BB(3, 0);
    bzr_u[c]       = BB(0, 1) + BB(1, 1);
    bzr_u[128 + c] = BB(2, 1) + BB(3, 1);
    bcx_n[c] = BB(4, 0);
    bcx_u[c] = BB(4, 1);
    bch_n[c] = BB(5, 0);
    bch_u[c] = BB(5, 1);
#undef BB
}

// ---------------------------------------------------------------------------
// fused GEMM: C = [A0|A1|A2|A3] @ W + bias, with epilogue modes:
//   mode 0 (ZR): cols<128 -> Z=sigmoid(v); cols>=128 -> HR = sigmoid(v) * H
//   mode 1 (CX): store v
//   mode 2 (CH): ht=tanh(v+CX); out = Z*H + (1-Z)*ht
#define BM 128
#define BN 128
#define BK 16
#define TM 8
#define TN 8

__device__ __forceinline__ float sigmoidf_(float x) { return 1.f / (1.f + expf(-x)); }

__global__ void __launch_bounds__(256, 2) gemm_kernel(
    const float* __restrict__ A0, const float* __restrict__ A1,
    const float* __restrict__ A2, const float* __restrict__ A3,
    const float* __restrict__ W, const float* __restrict__ bias,
    int M, int N, int nparts, int mode,
    const float* __restrict__ H, const float* __restrict__ Z, const float* __restrict__ CX,
    float* __restrict__ out0, float* __restrict__ out1) {
    __shared__ float As[BK][BM];
    __shared__ float Ws[BK][BN];
    int tid = threadIdx.x;
    int row0 = blockIdx.y * BM;
    int col0 = blockIdx.x * BN;

    float acc[TM][TN];
#pragma unroll
    for (int i = 0; i < TM; i++)
#pragma unroll
        for (int j = 0; j < TN; j++) acc[i][j] = 0.f;

    int tr = (tid >> 4) * TM;
    int tc = (tid & 15) * TN;
    int K = nparts * D;

    for (int k0 = 0; k0 < K; k0 += BK) {
        const float* Ap = (k0 < D) ? A0 : (k0 < 2 * D) ? A1 : (k0 < 3 * D) ? A2 : A3;
        int kk0 = k0 & (D - 1);
#pragma unroll
        for (int i = 0; i < 2; i++) {
            int idx = tid + i * 256;      // 0..511
            int r = idx >> 2;             // 0..127
            int kq = (idx & 3) * 4;       // 0,4,8,12
            int grow = row0 + r;
            float4 v = make_float4(0.f, 0.f, 0.f, 0.f);
            if (grow < M) v = *(const float4*)(Ap + (long)grow * D + kk0 + kq);
            As[kq + 0][r] = v.x; As[kq + 1][r] = v.y; As[kq + 2][r] = v.z; As[kq + 3][r] = v.w;
        }
#pragma unroll
        for (int i = 0; i < 2; i++) {
            int idx = tid + i * 256;
            int kr = idx >> 5;            // 0..15
            int cq = (idx & 31) * 4;      // 0..124
            *(float4*)&Ws[kr][cq] = *(const float4*)(W + (long)(k0 + kr) * N + col0 + cq);
        }
        __syncthreads();
#pragma unroll
        for (int kk = 0; kk < BK; kk++) {
            float a[TM], bfr[TN];
            *(float4*)&a[0]   = *(const float4*)&As[kk][tr];
            *(float4*)&a[4]   = *(const float4*)&As[kk][tr + 4];
            *(float4*)&bfr[0] = *(const float4*)&Ws[kk][tc];
            *(float4*)&bfr[4] = *(const float4*)&Ws[kk][tc + 4];
#pragma unroll
            for (int i = 0; i < TM; i++)
#pragma unroll
                for (int j = 0; j < TN; j++)
                    acc[i][j] = fmaf(a[i], bfr[j], acc[i][j]);
        }
        __syncthreads();
    }

#pragma unroll
    for (int i = 0; i < TM; i++) {
        int r = row0 + tr + i;
        if (r >= M) break;
        long rbase = (long)r * D;
#pragma unroll
        for (int j = 0; j < TN; j++) {
            int c = col0 + tc + j;
            float v = acc[i][j] + bias[c];
            if (mode == 0) {
                if (c < D) {
                    out0[rbase + c] = sigmoidf_(v);
                } else {
                    int cc = c - D;
                    float rr = sigmoidf_(v);
                    out1[rbase + cc] = rr * H[rbase + cc];
                }
            } else if (mode == 1) {
                out0[rbase + c] = v;
            } else {
                float ht = tanhf(v + CX[rbase + c]);
                float z = Z[rbase + c];
                out0[rbase + c] = z * H[rbase + c] + (1.f - z) * ht;
            }
        }
    }
}

// ---------------------------------------------------------------------------
extern "C" void kernel_launch(void* const* d_in, const int* in_sizes, int n_in,
                              void* d_out, int out_size) {
    const float* x_user = (const float*)d_in[0];
    const float* x_news = (const float*)d_in[1];
    const float* h_user = (const float*)d_in[2];
    const float* h_news = (const float*)d_in[3];
    const float* Wl     = (const float*)d_in[4];
    const float* Wr     = (const float*)d_in[5];
    const float* bb     = (const float*)d_in[6];
    const int* src_un   = (const int*)d_in[7];
    const int* dst_un   = (const int*)d_in[8];
    const int* src_nu   = (const int*)d_in[9];
    const int* dst_nu   = (const int*)d_in[10];

    int NU = in_sizes[0] / D;
    int NN = in_sizes[1] / D;
    int E1 = in_sizes[7];
    int E2 = in_sizes[9];

    float* base = nullptr;
    int* deg = nullptr;
    cudaGetSymbolAddress((void**)&base, g_buf);
    cudaGetSymbolAddress((void**)&deg, g_deg);

    float* Axn = base + 0 * SZ;
    float* Ahn = base + 1 * SZ;
    float* Axu = base + 2 * SZ;
    float* Ahu = base + 3 * SZ;
    float* Acn = base + 4 * SZ;
    float* Acu = base + 5 * SZ;
    float* Zn  = base + 6 * SZ;
    float* Zu  = base + 7 * SZ;
    float* CXn = base + 8 * SZ;
    float* CXu = base + 9 * SZ;
    float* HRn = base + 10 * SZ;
    float* HRu = base + 11 * SZ;
    float* wp    = base + 12 * SZ;
    float* Wzr_n = wp;               wp += 512 * 256;
    float* Wzr_u = wp;               wp += 512 * 256;
    float* Wcx_n = wp;               wp += 256 * 128;
    float* Wcx_u = wp;               wp += 256 * 128;
    float* Wch_n = wp;               wp += 256 * 128;
    float* Wch_u = wp;               wp += 256 * 128;
    float* bzr_n = wp;               wp += 256;
    float* bzr_u = wp;               wp += 256;
    float* bcx_n = wp;               wp += 128;
    float* bcx_u = wp;               wp += 128;
    float* bch_n = wp;               wp += 128;
    float* bch_u = wp;               wp += 128;

    int* deg_n = deg;
    int* deg_u = deg + MAXN;

    float* out_u = (float*)d_out;                 // h_user' first
    float* out_n = (float*)d_out + (long)NU * D;  // then h_news'

    // 1) zero accumulators + degrees
    zero_kernel<<<4096, 256>>>((float4*)base, (6 * SZ) / 4, deg, NU + NN);

    // 2) stack weights & biases
    build_wzr<<<(512 * 256 + 255) / 256, 256>>>(Wl, Wr, Wzr_n, 0);
    build_wzr<<<(512 * 256 + 255) / 256, 256>>>(Wl, Wr, Wzr_u, 1);
    build_w2<<<(256 * 128 + 255) / 256, 256>>>(Wl, Wr, Wcx_n, 4, 0);
    build_w2<<<(256 * 128 + 255) / 256, 256>>>(Wl, Wr, Wcx_u, 4, 1);
    build_w2<<<(256 * 128 + 255) / 256, 256>>>(Wl, Wr, Wch_n, 5, 0);
    build_w2<<<(256 * 128 + 255) / 256, 256>>>(Wl, Wr, Wch_u, 5, 1);
    build_bias<<<1, 128>>>(bb, bzr_n, bzr_u, bcx_n, bcx_u, bch_n, bch_u);

    // 3) degrees
    count_deg<<<(E1 + 255) / 256, 256>>>(dst_un, E1, deg_n);
    count_deg<<<(E2 + 255) / 256, 256>>>(dst_nu, E2, deg_u);

    // 4) aggregate x and h features (fused per edge direction)
    long thr1 = (long)E1 * 32, thr2 = (long)E2 * 32;
    agg2_kernel<<<(int)((thr1 + 255) / 256), 256>>>(x_user, h_user, src_un, dst_un, E1, Axn, Ahn);
    agg2_kernel<<<(int)((thr2 + 255) / 256), 256>>>(x_news, h_news, src_nu, dst_nu, E2, Axu, Ahu);
    norm2_kernel<<<(NN * 32 + 255) / 256, 256>>>(Axn, Ahn, deg_n, NN);
    norm2_kernel<<<(NU * 32 + 255) / 256, 256>>>(Axu, Ahu, deg_u, NU);

    // 5) z/r gates (K=512, N=256) with fused sigmoid + h*r epilogue
    dim3 gzr(2, (unsigned)((MAXN + BM - 1) / BM));
    dim3 g1(1, (unsigned)((MAXN + BM - 1) / BM));
    gemm_kernel<<<gzr, 256>>>(Axn, x_news, Ahn, h_news, Wzr_n, bzr_n, NN, 256, 4, 0,
                              h_news, nullptr, nullptr, Zn, HRn);
    gemm_kernel<<<gzr, 256>>>(Axu, x_user, Ahu, h_user, Wzr_u, bzr_u, NU, 256, 4, 0,
                              h_user, nullptr, nullptr, Zu, HRu);

    // 6) cx (K=256, N=128)
    gemm_kernel<<<g1, 256>>>(Axn, x_news, nullptr, nullptr, Wcx_n, bcx_n, NN, 128, 2, 1,
                             nullptr, nullptr, nullptr, CXn, nullptr);
    gemm_kernel<<<g1, 256>>>(Axu, x_user, nullptr, nullptr, Wcx_u, bcx_u, NU, 128, 2, 1,
                             nullptr, nullptr, nullptr, CXu, nullptr);

    // 7) aggregate h*r
    agg1_kernel<<<(int)((thr1 + 255) / 256), 256>>>(HRu, src_un, dst_un, E1, Acn);
    agg1_kernel<<<(int)((thr2 + 255) / 256), 256>>>(HRn, src_nu, dst_nu, E2, Acu);
    norm1_kernel<<<(NN * 32 + 255) / 256, 256>>>(Acn, deg_n, NN);
    norm1_kernel<<<(NU * 32 + 255) / 256, 256>>>(Acu, deg_u, NU);

    // 8) ch GEMM with fused tanh + GRU-update epilogue, writing final output
    gemm_kernel<<<g1, 256>>>(Acu, HRu, nullptr, nullptr, Wch_u, bch_u, NU, 128, 2, 2,
                             h_user, Zu, CXu, out_u, nullptr);
    gemm_kernel<<<g1, 256>>>(Acn, HRn, nullptr, nullptr, Wch_n, bch_n, NN, 128, 2, 2,
                             h_news, Zn, CXn, out_n, nullptr);
}